// round 7
// baseline (speedup 1.0000x reference)
#include <cuda_runtime.h>

// SheafLoss: B=4 T=1024 P=16 D=64 R=32 K=64, TAU=1
// d_in[0]=m (B,T,P,D) f32, d_in[1]=w (B,T,P) f32,
// d_in[2]=p (B,T,P,K) f32, d_in[3]=patch_centers (R,D) f32
// out: scalar f32

#define BT    4096
#define P_    16
#define D_    64
#define R_    32
#define K_    64
#define TPC   2
#define LN2   0.6931471805599453f

__device__ double g_acc;
__device__ unsigned int g_done;
__device__ float  g_omega[R_ * R_];
__device__ float  g_cn[R_];
__device__ float  g_hs[R_];     // hs[r] = sum_{s != r} omega[r][s]

__device__ __forceinline__ void cp_async16(unsigned saddr, const void* gaddr) {
    asm volatile("cp.async.ca.shared.global [%0], [%1], 16;" :: "r"(saddr), "l"(gaddr));
}
__device__ __forceinline__ void cp_commit() {
    asm volatile("cp.async.commit_group;");
}

// ---------------------------------------------------------------------------
// Setup: 4 blocks x 256 threads; block b handles rows [8b, 8b+8).
// ---------------------------------------------------------------------------
__global__ void __launch_bounds__(256) sheaf_setup_kernel(const float* __restrict__ gc) {
    __shared__ float sc[R_][D_ + 1];
    const int tid = threadIdx.x;
    for (int i = tid; i < R_ * D_; i += 256) sc[i >> 6][i & 63] = gc[i];
    __syncthreads();
    const int r = blockIdx.x * 8 + (tid >> 5);
    const int s = tid & 31;
    float cd = 0.f;
#pragma unroll 8
    for (int d = 0; d < D_; d++) {
        float df = sc[r][d] - sc[s][d];
        cd = fmaf(df, df, cd);
    }
    float omv = expf(-cd);
    g_omega[r * R_ + s] = omv;
    float hs = omv;
#pragma unroll
    for (int off = 16; off; off >>= 1)
        hs += __shfl_xor_sync(0xffffffffu, hs, off);
    if (s == 0) g_hs[r] = hs - 1.0f;
    float t = sc[r][s] * sc[r][s] + sc[r][s + 32] * sc[r][s + 32];
#pragma unroll
    for (int off = 16; off; off >>= 1)
        t += __shfl_xor_sync(0xffffffffu, t, off);
    if (s == 1) g_cn[r] = t;
    if (r == 0 && s == 2) { g_acc = 0.0; g_done = 0u; }
}

// ---------------------------------------------------------------------------
// Main: one CTA per 2 tiles, 256 threads, cp.async double-buffered m/p.
// ---------------------------------------------------------------------------
__global__ void __launch_bounds__(256, 5) sheaf_kernel(
    const float* __restrict__ gm,
    const float* __restrict__ gw,
    const float* __restrict__ gp,
    const float* __restrict__ gc,
    float* __restrict__ gout)
{
    __shared__ float  s_c[R_][68];        // centers row-major, 16B rows
    __shared__ float4 s_m[2][256];        // double-buffered m tile
    __shared__ float4 s_p[2][256];        // double-buffered p tile
    __shared__ float  s_w[2][P_];
    __shared__ float  s_sm[P_][R_ + 1];
    __shared__ float2 s_pb[R_][R_];
    __shared__ float  s_cn[R_];
    __shared__ float  s_hs[R_];
    __shared__ float  s_red[8];

    const int tid  = threadIdx.x;
    const int lane = tid & 31;
    const int wid  = tid >> 5;
    const int bt0  = blockIdx.x * TPC;

    // per-CTA constants
    for (int i = tid; i < R_ * D_; i += 256) s_c[i >> 6][i & 63] = gc[i];
    if (tid < R_) { s_cn[tid] = g_cn[tid]; s_hs[tid] = g_hs[tid]; }

    // prologue: async-copy tile 0, prefetch w0
    {
        unsigned sm0 = (unsigned)__cvta_generic_to_shared(&s_m[0][tid]);
        unsigned sp0 = (unsigned)__cvta_generic_to_shared(&s_p[0][tid]);
        cp_async16(sm0, (const float4*)(gm + (size_t)bt0 * 1024) + tid);
        cp_async16(sp0, (const float4*)(gp + (size_t)bt0 * 1024) + tid);
        cp_commit();
    }
    float pw = (tid < P_) ? gw[(size_t)bt0 * P_ + tid] : 0.f;

    float lacc = 0.f;   // per-lane, log2 domain
    float eacc = 0.f;   // lane-uniform per warp, log2 domain

#pragma unroll
    for (int t = 0; t < TPC; t++) {
        // issue copies for t+1 before waiting on t
        if (t + 1 < TPC) {
            const int bt1 = bt0 + t + 1;
            unsigned sm1 = (unsigned)__cvta_generic_to_shared(&s_m[t + 1][tid]);
            unsigned sp1 = (unsigned)__cvta_generic_to_shared(&s_p[t + 1][tid]);
            cp_async16(sm1, (const float4*)(gm + (size_t)bt1 * 1024) + tid);
            cp_async16(sp1, (const float4*)(gp + (size_t)bt1 * 1024) + tid);
            cp_commit();
        }
        if (t + 1 < TPC) asm volatile("cp.async.wait_group 1;");
        else             asm volatile("cp.async.wait_group 0;");
        if (tid < P_) s_w[t][tid] = pw;
        __syncthreads();   // buf t visible; also: all warps done pair(t-1)
        if (t + 1 < TPC && tid < P_) pw = gw[(size_t)(bt0 + t + 1) * P_ + tid];

        const float* smt = (const float*)s_m[t];
        const float* spt = (const float*)s_p[t];

        // ---- step 1: logits = 2*m.c - |c|^2; 8 warps x 2 patches; lane = r ----
        {
            const int p0 = wid, p1 = wid + 8;
            const int r = lane;
            float a0 = 0.f, a1 = 0.f;
#pragma unroll
            for (int d = 0; d < D_; d += 4) {
                float4 cv  = *(const float4*)&s_c[r][d];
                float4 mv0 = *(const float4*)&smt[p0 * D_ + d];
                float4 mv1 = *(const float4*)&smt[p1 * D_ + d];
                a0 = fmaf(mv0.x, cv.x, fmaf(mv0.y, cv.y, fmaf(mv0.z, cv.z, fmaf(mv0.w, cv.w, a0))));
                a1 = fmaf(mv1.x, cv.x, fmaf(mv1.y, cv.y, fmaf(mv1.z, cv.z, fmaf(mv1.w, cv.w, a1))));
            }
            const float cn = s_cn[r];
            float l0 = fmaf(2.f, a0, -cn);
            float l1 = fmaf(2.f, a1, -cn);
            float mx0 = l0, mx1 = l1;
#pragma unroll
            for (int off = 16; off; off >>= 1) {
                mx0 = fmaxf(mx0, __shfl_xor_sync(0xffffffffu, mx0, off));
                mx1 = fmaxf(mx1, __shfl_xor_sync(0xffffffffu, mx1, off));
            }
            float e0 = __expf(l0 - mx0);
            float e1 = __expf(l1 - mx1);
            float sm0 = e0, sm1 = e1;
#pragma unroll
            for (int off = 16; off; off >>= 1) {
                sm0 += __shfl_xor_sync(0xffffffffu, sm0, off);
                sm1 += __shfl_xor_sync(0xffffffffu, sm1, off);
            }
            s_sm[p0][lane] = e0 * (s_w[t][p0] / sm0);
            s_sm[p1][lane] = e1 * (s_w[t][p1] / sm1);
        }
        __syncthreads();

        // ---- step 3: total-mass fold + p_bar + E_r (log2 domain) ----
        {
            float acc[4][2] = {{0.f,0.f},{0.f,0.f},{0.f,0.f},{0.f,0.f}};
#pragma unroll
            for (int pp = 0; pp < P_; pp++) {
                float sp0 = spt[pp * K_ + lane];
                float sp1 = spt[pp * K_ + lane + 32];
#pragma unroll
                for (int j = 0; j < 4; j++) {
                    float g = s_sm[pp][wid + 8 * j];
                    acc[j][0] = fmaf(sp0, g, acc[j][0]);
                    acc[j][1] = fmaf(sp1, g, acc[j][1]);
                }
            }
#pragma unroll
            for (int j = 0; j < 4; j++) {
                const int r = wid + 8 * j;
                float v = (lane < P_) ? s_sm[lane][r] : 0.f;
#pragma unroll
                for (int off = 16; off; off >>= 1)
                    v += __shfl_xor_sync(0xffffffffu, v, off);
                float tm = 1.0f / (v + 1e-6f);
                float pb0 = acc[j][0] * tm;
                float pb1 = acc[j][1] * tm;
                s_pb[r][lane] = make_float2(pb0, pb1);
                float e = fmaf(pb0, __log2f(pb0 + 1e-8f), pb1 * __log2f(pb1 + 1e-8f));
#pragma unroll
                for (int off = 16; off; off >>= 1)
                    e += __shfl_xor_sync(0xffffffffu, e, off);
                eacc = fmaf(e, s_hs[r], eacc);
            }
        }
        __syncthreads();

        // ---- pair loop: rows {w, 15-w, 16+w, 31-w} => 62 pairs/warp ----
        // eps folded into hoisted pr2 (error ~1e-5 rel, under 1e-3 budget).
        {
            const int rows[4] = { wid, 15 - wid, 16 + wid, 31 - wid };
#pragma unroll
            for (int i = 0; i < 4; i++) {
                const int r = rows[i];
                float2 prv = s_pb[r][lane];
                const float pr2x = fmaf(0.5f, prv.x, 1e-8f);
                const float pr2y = fmaf(0.5f, prv.y, 1e-8f);
                const float* omrow = &g_omega[r * R_];
#pragma unroll 2
                for (int s = r + 1; s < R_; s++) {
                    float2 ps = s_pb[s][lane];
                    float om = __ldg(&omrow[s]);
                    float m0 = fmaf(0.5f, ps.x, pr2x);
                    float m1 = fmaf(0.5f, ps.y, pr2y);
                    float tt = fmaf(m0, __log2f(m0), m1 * __log2f(m1));
                    lacc = fmaf(om, tt, lacc);
                }
            }
        }
    }

    // ---- final reduction + last-CTA writeout (all in log2, scale once) ----
#pragma unroll
    for (int off = 16; off; off >>= 1)
        lacc += __shfl_xor_sync(0xffffffffu, lacc, off);
    if (lane == 0) s_red[wid] = fmaf(0.5f, eacc, -lacc) * LN2;
    __syncthreads();
    if (tid == 0) {
        float a = 0.f;
#pragma unroll
        for (int i = 0; i < 8; i++) a += s_red[i];
        atomicAdd(&g_acc, (double)a);
        __threadfence();
        unsigned int ticket = atomicAdd(&g_done, 1u);
        if (ticket == gridDim.x - 1) {
            double total = *(volatile double*)&g_acc;
            gout[0] = (float)(total / (496.0 + 1e-8));
        }
    }
}

extern "C" void kernel_launch(void* const* d_in, const int* in_sizes, int n_in,
                              void* d_out, int out_size) {
    const float* m = (const float*)d_in[0];
    const float* w = (const float*)d_in[1];
    const float* p = (const float*)d_in[2];
    const float* c = (const float*)d_in[3];
    float* out = (float*)d_out;
    (void)in_sizes; (void)n_in; (void)out_size;

    sheaf_setup_kernel<<<4, 256>>>(c);
    sheaf_kernel<<<BT / TPC, 256>>>(m, w, p, c, out);
}

// round 8
// speedup vs baseline: 1.0004x; 1.0004x over previous
#include <cuda_runtime.h>

// SheafLoss: B=4 T=1024 P=16 D=64 R=32 K=64, TAU=1
// d_in[0]=m (B,T,P,D) f32, d_in[1]=w (B,T,P) f32,
// d_in[2]=p (B,T,P,K) f32, d_in[3]=patch_centers (R,D) f32
// out: scalar f32

#define BT    4096
#define P_    16
#define D_    64
#define R_    32
#define K_    64
#define TPC   2
#define LN2   0.6931471805599453f

__device__ double g_acc;
__device__ unsigned int g_done;
__device__ float  g_omega[R_ * R_];
__device__ float  g_cn[R_];
__device__ float  g_hs[R_];     // hs[r] = sum_{s != r} omega[r][s]

__device__ __forceinline__ void cp_async16(unsigned saddr, const void* gaddr) {
    asm volatile("cp.async.ca.shared.global [%0], [%1], 16;" :: "r"(saddr), "l"(gaddr));
}
__device__ __forceinline__ void cp_commit() {
    asm volatile("cp.async.commit_group;");
}

// ---------------------------------------------------------------------------
// Setup: 4 blocks x 256 threads; block b handles rows [8b, 8b+8).
// ---------------------------------------------------------------------------
__global__ void __launch_bounds__(256) sheaf_setup_kernel(const float* __restrict__ gc) {
    __shared__ float sc[R_][D_ + 1];
    const int tid = threadIdx.x;
    for (int i = tid; i < R_ * D_; i += 256) sc[i >> 6][i & 63] = gc[i];
    __syncthreads();
    const int r = blockIdx.x * 8 + (tid >> 5);
    const int s = tid & 31;
    float cd = 0.f;
#pragma unroll 8
    for (int d = 0; d < D_; d++) {
        float df = sc[r][d] - sc[s][d];
        cd = fmaf(df, df, cd);
    }
    float omv = expf(-cd);
    g_omega[r * R_ + s] = omv;
    float hs = omv;
#pragma unroll
    for (int off = 16; off; off >>= 1)
        hs += __shfl_xor_sync(0xffffffffu, hs, off);
    if (s == 0) g_hs[r] = hs - 1.0f;
    float t = sc[r][s] * sc[r][s] + sc[r][s + 32] * sc[r][s + 32];
#pragma unroll
    for (int off = 16; off; off >>= 1)
        t += __shfl_xor_sync(0xffffffffu, t, off);
    if (s == 1) g_cn[r] = t;
    if (r == 0 && s == 2) { g_acc = 0.0; g_done = 0u; }
}

// ---------------------------------------------------------------------------
// Main: one CTA per 2 tiles, 256 threads.
// Lane k-pairing everywhere: lane owns k-slice (2*lane, 2*lane+1).
// Warp row set everywhere: rows {w, 15-w, 16+w, 31-w} (sorted for w in 0..7).
// ---------------------------------------------------------------------------
__global__ void __launch_bounds__(256, 5) sheaf_kernel(
    const float* __restrict__ gm,
    const float* __restrict__ gw,
    const float* __restrict__ gp,
    const float* __restrict__ gc,
    float* __restrict__ gout)
{
    __shared__ float  s_c[R_][68];        // centers row-major, 16B rows
    __shared__ float4 s_m[2][256];        // double-buffered m tile
    __shared__ float4 s_p[2][256];        // double-buffered p tile
    __shared__ float  s_w[2][P_];
    __shared__ float  s_sm[P_][R_ + 1];
    __shared__ float2 s_pb[R_][R_];       // [r][lane] = (p_bar[2*lane], p_bar[2*lane+1])
    __shared__ float  s_cn[R_];
    __shared__ float  s_hs[R_];
    __shared__ float  s_red[8];

    const int tid  = threadIdx.x;
    const int lane = tid & 31;
    const int wid  = tid >> 5;
    const int bt0  = blockIdx.x * TPC;

    const int r0 = wid, r1 = 15 - wid, r2 = 16 + wid, r3 = 31 - wid;

    // per-CTA constants
    for (int i = tid; i < R_ * D_; i += 256) s_c[i >> 6][i & 63] = gc[i];
    if (tid < R_) { s_cn[tid] = g_cn[tid]; s_hs[tid] = g_hs[tid]; }

    // prologue: async-copy tile 0
    {
        unsigned sm0 = (unsigned)__cvta_generic_to_shared(&s_m[0][tid]);
        unsigned sp0 = (unsigned)__cvta_generic_to_shared(&s_p[0][tid]);
        cp_async16(sm0, (const float4*)(gm + (size_t)bt0 * 1024) + tid);
        cp_async16(sp0, (const float4*)(gp + (size_t)bt0 * 1024) + tid);
        cp_commit();
    }
    float pw = (tid < P_) ? gw[(size_t)bt0 * P_ + tid] : 0.f;

    float lacc = 0.f;   // per-lane, log2 domain
    float eacc = 0.f;   // lane-uniform per warp, log2 domain

#pragma unroll
    for (int t = 0; t < TPC; t++) {
        if (t + 1 < TPC) {
            const int bt1 = bt0 + t + 1;
            unsigned sm1 = (unsigned)__cvta_generic_to_shared(&s_m[t + 1][tid]);
            unsigned sp1 = (unsigned)__cvta_generic_to_shared(&s_p[t + 1][tid]);
            cp_async16(sm1, (const float4*)(gm + (size_t)bt1 * 1024) + tid);
            cp_async16(sp1, (const float4*)(gp + (size_t)bt1 * 1024) + tid);
            cp_commit();
            asm volatile("cp.async.wait_group 1;");
        } else {
            asm volatile("cp.async.wait_group 0;");
        }
        if (tid < P_) s_w[t][tid] = pw;
        __syncthreads();   // buf t visible; all warps done with pair(t-1)
        if (t + 1 < TPC && tid < P_) pw = gw[(size_t)(bt0 + t + 1) * P_ + tid];

        const float* smt = (const float*)s_m[t];
        const float* spt = (const float*)s_p[t];

        // ---- step 1: logits = 2*m.c - |c|^2; 8 warps x 2 patches; lane = r ----
        {
            const int p0 = wid, p1 = wid + 8;
            const int r = lane;
            float a0 = 0.f, a1 = 0.f;
#pragma unroll
            for (int d = 0; d < D_; d += 4) {
                float4 cv  = *(const float4*)&s_c[r][d];
                float4 mv0 = *(const float4*)&smt[p0 * D_ + d];
                float4 mv1 = *(const float4*)&smt[p1 * D_ + d];
                a0 = fmaf(mv0.x, cv.x, fmaf(mv0.y, cv.y, fmaf(mv0.z, cv.z, fmaf(mv0.w, cv.w, a0))));
                a1 = fmaf(mv1.x, cv.x, fmaf(mv1.y, cv.y, fmaf(mv1.z, cv.z, fmaf(mv1.w, cv.w, a1))));
            }
            const float cn = s_cn[r];
            float l0 = fmaf(2.f, a0, -cn);
            float l1 = fmaf(2.f, a1, -cn);
            float mx0 = l0, mx1 = l1;
#pragma unroll
            for (int off = 16; off; off >>= 1) {
                mx0 = fmaxf(mx0, __shfl_xor_sync(0xffffffffu, mx0, off));
                mx1 = fmaxf(mx1, __shfl_xor_sync(0xffffffffu, mx1, off));
            }
            float e0 = __expf(l0 - mx0);
            float e1 = __expf(l1 - mx1);
            float sm0 = e0, sm1 = e1;
#pragma unroll
            for (int off = 16; off; off >>= 1) {
                sm0 += __shfl_xor_sync(0xffffffffu, sm0, off);
                sm1 += __shfl_xor_sync(0xffffffffu, sm1, off);
            }
            s_sm[p0][lane] = e0 * (s_w[t][p0] / sm0);
            s_sm[p1][lane] = e1 * (s_w[t][p1] / sm1);
        }
        __syncthreads();

        // ---- step 3: p_bar + E_r; rows {r0,r1,r2,r3}; LDS.64 k-pairs ----
        float pr2x[4], pr2y[4];
        {
            const int rows[4] = { r0, r1, r2, r3 };
            float acc0[4] = {0.f,0.f,0.f,0.f};
            float acc1[4] = {0.f,0.f,0.f,0.f};
#pragma unroll
            for (int pp = 0; pp < P_; pp++) {
                float2 sp = *(const float2*)&spt[pp * K_ + 2 * lane];
#pragma unroll
                for (int j = 0; j < 4; j++) {
                    float g = s_sm[pp][rows[j]];
                    acc0[j] = fmaf(sp.x, g, acc0[j]);
                    acc1[j] = fmaf(sp.y, g, acc1[j]);
                }
            }
#pragma unroll
            for (int j = 0; j < 4; j++) {
                const int r = rows[j];
                float v = (lane < P_) ? s_sm[lane][r] : 0.f;
#pragma unroll
                for (int off = 16; off; off >>= 1)
                    v += __shfl_xor_sync(0xffffffffu, v, off);
                float tm = 1.0f / (v + 1e-6f);
                float pb0 = acc0[j] * tm;
                float pb1 = acc1[j] * tm;
                s_pb[r][lane] = make_float2(pb0, pb1);
                pr2x[j] = fmaf(0.5f, pb0, 1e-8f);
                pr2y[j] = fmaf(0.5f, pb1, 1e-8f);
                float e = fmaf(pb0, __log2f(pb0 + 1e-8f), pb1 * __log2f(pb1 + 1e-8f));
#pragma unroll
                for (int off = 16; off; off >>= 1)
                    e += __shfl_xor_sync(0xffffffffu, e, off);
                eacc = fmaf(e, s_hs[r], eacc);
            }
        }
        __syncthreads();

        // ---- pair loop: 4 branch-free segments; ps loaded once per s ----
        // seg1: s in (r0,r1]   -> pairs with r0
        // seg2: s in (r1,r2]   -> pairs with r0,r1
        // seg3: s in (r2,r3]   -> pairs with r0,r1,r2
        // seg4: s in (r3,31]   -> pairs with r0,r1,r2,r3
        {
            for (int s = r0 + 1; s <= r1; s++) {
                float2 ps = s_pb[s][lane];
                float m0 = fmaf(0.5f, ps.x, pr2x[0]);
                float m1 = fmaf(0.5f, ps.y, pr2y[0]);
                float tt = fmaf(m0, __log2f(m0), m1 * __log2f(m1));
                lacc = fmaf(__ldg(&g_omega[r0 * R_ + s]), tt, lacc);
            }
            for (int s = r1 + 1; s <= r2; s++) {
                float2 ps = s_pb[s][lane];
                float m0 = fmaf(0.5f, ps.x, pr2x[0]);
                float m1 = fmaf(0.5f, ps.y, pr2y[0]);
                float tt = fmaf(m0, __log2f(m0), m1 * __log2f(m1));
                lacc = fmaf(__ldg(&g_omega[r0 * R_ + s]), tt, lacc);
                m0 = fmaf(0.5f, ps.x, pr2x[1]);
                m1 = fmaf(0.5f, ps.y, pr2y[1]);
                tt = fmaf(m0, __log2f(m0), m1 * __log2f(m1));
                lacc = fmaf(__ldg(&g_omega[r1 * R_ + s]), tt, lacc);
            }
            for (int s = r2 + 1; s <= r3; s++) {
                float2 ps = s_pb[s][lane];
                float m0 = fmaf(0.5f, ps.x, pr2x[0]);
                float m1 = fmaf(0.5f, ps.y, pr2y[0]);
                float tt = fmaf(m0, __log2f(m0), m1 * __log2f(m1));
                lacc = fmaf(__ldg(&g_omega[r0 * R_ + s]), tt, lacc);
                m0 = fmaf(0.5f, ps.x, pr2x[1]);
                m1 = fmaf(0.5f, ps.y, pr2y[1]);
                tt = fmaf(m0, __log2f(m0), m1 * __log2f(m1));
                lacc = fmaf(__ldg(&g_omega[r1 * R_ + s]), tt, lacc);
                m0 = fmaf(0.5f, ps.x, pr2x[2]);
                m1 = fmaf(0.5f, ps.y, pr2y[2]);
                tt = fmaf(m0, __log2f(m0), m1 * __log2f(m1));
                lacc = fmaf(__ldg(&g_omega[r2 * R_ + s]), tt, lacc);
            }
            for (int s = r3 + 1; s < R_; s++) {
                float2 ps = s_pb[s][lane];
#pragma unroll
                for (int j = 0; j < 4; j++) {
                    const int rj = (j == 0) ? r0 : (j == 1) ? r1 : (j == 2) ? r2 : r3;
                    float m0 = fmaf(0.5f, ps.x, pr2x[j]);
                    float m1 = fmaf(0.5f, ps.y, pr2y[j]);
                    float tt = fmaf(m0, __log2f(m0), m1 * __log2f(m1));
                    lacc = fmaf(__ldg(&g_omega[rj * R_ + s]), tt, lacc);
                }
            }
        }
    }

    // ---- final reduction + last-CTA writeout (log2 domain, scale once) ----
#pragma unroll
    for (int off = 16; off; off >>= 1)
        lacc += __shfl_xor_sync(0xffffffffu, lacc, off);
    if (lane == 0) s_red[wid] = fmaf(0.5f, eacc, -lacc) * LN2;
    __syncthreads();
    if (tid == 0) {
        float a = 0.f;
#pragma unroll
        for (int i = 0; i < 8; i++) a += s_red[i];
        atomicAdd(&g_acc, (double)a);
        __threadfence();
        unsigned int ticket = atomicAdd(&g_done, 1u);
        if (ticket == gridDim.x - 1) {
            double total = *(volatile double*)&g_acc;
            gout[0] = (float)(total / (496.0 + 1e-8));
        }
    }
}

extern "C" void kernel_launch(void* const* d_in, const int* in_sizes, int n_in,
                              void* d_out, int out_size) {
    const float* m = (const float*)d_in[0];
    const float* w = (const float*)d_in[1];
    const float* p = (const float*)d_in[2];
    const float* c = (const float*)d_in[3];
    float* out = (float*)d_out;
    (void)in_sizes; (void)n_in; (void)out_size;

    sheaf_setup_kernel<<<4, 256>>>(c);
    sheaf_kernel<<<BT / TPC, 256>>>(m, w, p, c, out);
}

// round 9
// speedup vs baseline: 1.0839x; 1.0835x over previous
#include <cuda_runtime.h>

// SheafLoss: B=4 T=1024 P=16 D=64 R=32 K=64, TAU=1
// d_in[0]=m (B,T,P,D) f32, d_in[1]=w (B,T,P) f32,
// d_in[2]=p (B,T,P,K) f32, d_in[3]=patch_centers (R,D) f32
// out: scalar f32

#define BT    4096
#define P_    16
#define D_    64
#define R_    32
#define K_    64
#define TPC   2
#define LN2   0.6931471805599453f

__device__ double g_acc;
__device__ unsigned int g_done;
__device__ float  g_omega[R_ * R_];
__device__ float  g_cn[R_];
__device__ float  g_hs[R_];     // hs[r] = sum_{s != r} omega[r][s]

__device__ __forceinline__ void cp_async16(unsigned saddr, const void* gaddr) {
    asm volatile("cp.async.ca.shared.global [%0], [%1], 16;" :: "r"(saddr), "l"(gaddr));
}
__device__ __forceinline__ void cp_commit() {
    asm volatile("cp.async.commit_group;");
}

// ---------------------------------------------------------------------------
// Setup: 4 blocks x 256 threads; block b handles rows [8b, 8b+8).
// ---------------------------------------------------------------------------
__global__ void __launch_bounds__(256) sheaf_setup_kernel(const float* __restrict__ gc) {
    __shared__ float sc[R_][D_ + 1];
    const int tid = threadIdx.x;
    for (int i = tid; i < R_ * D_; i += 256) sc[i >> 6][i & 63] = gc[i];
    __syncthreads();
    const int r = blockIdx.x * 8 + (tid >> 5);
    const int s = tid & 31;
    float cd = 0.f;
#pragma unroll 8
    for (int d = 0; d < D_; d++) {
        float df = sc[r][d] - sc[s][d];
        cd = fmaf(df, df, cd);
    }
    float omv = expf(-cd);
    g_omega[r * R_ + s] = omv;
    float hs = omv;
#pragma unroll
    for (int off = 16; off; off >>= 1)
        hs += __shfl_xor_sync(0xffffffffu, hs, off);
    if (s == 0) g_hs[r] = hs - 1.0f;
    float t = sc[r][s] * sc[r][s] + sc[r][s + 32] * sc[r][s + 32];
#pragma unroll
    for (int off = 16; off; off >>= 1)
        t += __shfl_xor_sync(0xffffffffu, t, off);
    if (s == 1) g_cn[r] = t;
    if (r == 0 && s == 2) { g_acc = 0.0; g_done = 0u; }
}

// ---------------------------------------------------------------------------
// Main: one CTA per 2 tiles, 256 threads, 6 CTAs/SM target.
// Lane k-pairing: lane owns k-slice (2*lane, 2*lane+1).
// Warp row set: {w, 15-w, 16+w, 31-w} (sorted ascending for w in 0..7).
// Omega rows live in registers; pair loop reads them via shfl.
// ---------------------------------------------------------------------------
__global__ void __launch_bounds__(256, 6) sheaf_kernel(
    const float* __restrict__ gm,
    const float* __restrict__ gw,
    const float* __restrict__ gp,
    const float* __restrict__ gc,
    float* __restrict__ gout)
{
    __shared__ float  s_c[R_][68];        // centers row-major, 16B rows
    __shared__ float4 s_m[2][256];        // double-buffered m tile
    __shared__ float4 s_p[2][256];        // double-buffered p tile
    __shared__ float  s_w[2][P_];
    __shared__ float  s_sm[P_][R_ + 1];
    __shared__ float2 s_pb[R_][R_];       // [r][lane] = (p_bar[2*lane], p_bar[2*lane+1])
    __shared__ float  s_cn[R_];
    __shared__ float  s_hs[R_];
    __shared__ float  s_red[8];

    const int tid  = threadIdx.x;
    const int lane = tid & 31;
    const int wid  = tid >> 5;
    const int bt0  = blockIdx.x * TPC;

    const int r0 = wid, r1 = 15 - wid, r2 = 16 + wid, r3 = 31 - wid;

    // per-CTA constants
    for (int i = tid; i < R_ * D_; i += 256) s_c[i >> 6][i & 63] = gc[i];
    if (tid < R_) { s_cn[tid] = g_cn[tid]; s_hs[tid] = g_hs[tid]; }

    // tile-invariant omega rows for this warp, register-resident
    const float om0 = g_omega[r0 * R_ + lane];
    const float om1 = g_omega[r1 * R_ + lane];
    const float om2 = g_omega[r2 * R_ + lane];
    const float om3 = g_omega[r3 * R_ + lane];

    // prologue: async-copy tile 0
    {
        unsigned sm0 = (unsigned)__cvta_generic_to_shared(&s_m[0][tid]);
        unsigned sp0 = (unsigned)__cvta_generic_to_shared(&s_p[0][tid]);
        cp_async16(sm0, (const float4*)(gm + (size_t)bt0 * 1024) + tid);
        cp_async16(sp0, (const float4*)(gp + (size_t)bt0 * 1024) + tid);
        cp_commit();
    }
    float pw = (tid < P_) ? gw[(size_t)bt0 * P_ + tid] : 0.f;

    float lacc = 0.f;   // per-lane, log2 domain
    float eacc = 0.f;   // lane-uniform per warp, log2 domain

#pragma unroll
    for (int t = 0; t < TPC; t++) {
        if (t + 1 < TPC) {
            const int bt1 = bt0 + t + 1;
            unsigned sm1 = (unsigned)__cvta_generic_to_shared(&s_m[t + 1][tid]);
            unsigned sp1 = (unsigned)__cvta_generic_to_shared(&s_p[t + 1][tid]);
            cp_async16(sm1, (const float4*)(gm + (size_t)bt1 * 1024) + tid);
            cp_async16(sp1, (const float4*)(gp + (size_t)bt1 * 1024) + tid);
            cp_commit();
            asm volatile("cp.async.wait_group 1;");
        } else {
            asm volatile("cp.async.wait_group 0;");
        }
        if (tid < P_) s_w[t][tid] = pw;
        __syncthreads();   // buf t visible; all warps done with pair(t-1)
        if (t + 1 < TPC && tid < P_) pw = gw[(size_t)(bt0 + t + 1) * P_ + tid];

        const float* smt = (const float*)s_m[t];
        const float* spt = (const float*)s_p[t];

        // ---- step 1: logits = 2*m.c - |c|^2; 8 warps x 2 patches; lane = r ----
        {
            const int p0 = wid, p1 = wid + 8;
            const int r = lane;
            float a0 = 0.f, a1 = 0.f;
#pragma unroll
            for (int d = 0; d < D_; d += 4) {
                float4 cv  = *(const float4*)&s_c[r][d];
                float4 mv0 = *(const float4*)&smt[p0 * D_ + d];
                float4 mv1 = *(const float4*)&smt[p1 * D_ + d];
                a0 = fmaf(mv0.x, cv.x, fmaf(mv0.y, cv.y, fmaf(mv0.z, cv.z, fmaf(mv0.w, cv.w, a0))));
                a1 = fmaf(mv1.x, cv.x, fmaf(mv1.y, cv.y, fmaf(mv1.z, cv.z, fmaf(mv1.w, cv.w, a1))));
            }
            const float cn = s_cn[r];
            float l0 = fmaf(2.f, a0, -cn);
            float l1 = fmaf(2.f, a1, -cn);
            float mx0 = l0, mx1 = l1;
#pragma unroll
            for (int off = 16; off; off >>= 1) {
                mx0 = fmaxf(mx0, __shfl_xor_sync(0xffffffffu, mx0, off));
                mx1 = fmaxf(mx1, __shfl_xor_sync(0xffffffffu, mx1, off));
            }
            float e0 = __expf(l0 - mx0);
            float e1 = __expf(l1 - mx1);
            float sm0 = e0, sm1 = e1;
#pragma unroll
            for (int off = 16; off; off >>= 1) {
                sm0 += __shfl_xor_sync(0xffffffffu, sm0, off);
                sm1 += __shfl_xor_sync(0xffffffffu, sm1, off);
            }
            s_sm[p0][lane] = e0 * (s_w[t][p0] / sm0);
            s_sm[p1][lane] = e1 * (s_w[t][p1] / sm1);
        }
        __syncthreads();

        // ---- step 3: p_bar + E_r; rows {r0..r3}; LDS.64 k-pairs ----
        float pr2x[4], pr2y[4];
        {
            const int rows[4] = { r0, r1, r2, r3 };
            float acc0[4] = {0.f,0.f,0.f,0.f};
            float acc1[4] = {0.f,0.f,0.f,0.f};
#pragma unroll
            for (int pp = 0; pp < P_; pp++) {
                float2 sp = *(const float2*)&spt[pp * K_ + 2 * lane];
#pragma unroll
                for (int j = 0; j < 4; j++) {
                    float g = s_sm[pp][rows[j]];
                    acc0[j] = fmaf(sp.x, g, acc0[j]);
                    acc1[j] = fmaf(sp.y, g, acc1[j]);
                }
            }
#pragma unroll
            for (int j = 0; j < 4; j++) {
                const int r = rows[j];
                float v = (lane < P_) ? s_sm[lane][r] : 0.f;
#pragma unroll
                for (int off = 16; off; off >>= 1)
                    v += __shfl_xor_sync(0xffffffffu, v, off);
                float tm = 1.0f / (v + 1e-6f);
                float pb0 = acc0[j] * tm;
                float pb1 = acc1[j] * tm;
                s_pb[r][lane] = make_float2(pb0, pb1);
                pr2x[j] = fmaf(0.5f, pb0, 1e-8f);
                pr2y[j] = fmaf(0.5f, pb1, 1e-8f);
                float e = fmaf(pb0, __log2f(pb0 + 1e-8f), pb1 * __log2f(pb1 + 1e-8f));
#pragma unroll
                for (int off = 16; off; off >>= 1)
                    e += __shfl_xor_sync(0xffffffffu, e, off);
                eacc = fmaf(e, s_hs[r], eacc);
            }
        }
        __syncthreads();

        // ---- pair loop: 4 branch-free segments; ps loaded once per s;
        //      omega fetched from registers via shfl (no LDG). ----
        {
            for (int s = r0 + 1; s <= r1; s++) {
                float2 ps = s_pb[s][lane];
                float m0 = fmaf(0.5f, ps.x, pr2x[0]);
                float m1 = fmaf(0.5f, ps.y, pr2y[0]);
                float tt = fmaf(m0, __log2f(m0), m1 * __log2f(m1));
                lacc = fmaf(__shfl_sync(0xffffffffu, om0, s), tt, lacc);
            }
            for (int s = r1 + 1; s <= r2; s++) {
                float2 ps = s_pb[s][lane];
                float m0 = fmaf(0.5f, ps.x, pr2x[0]);
                float m1 = fmaf(0.5f, ps.y, pr2y[0]);
                float tt = fmaf(m0, __log2f(m0), m1 * __log2f(m1));
                lacc = fmaf(__shfl_sync(0xffffffffu, om0, s), tt, lacc);
                m0 = fmaf(0.5f, ps.x, pr2x[1]);
                m1 = fmaf(0.5f, ps.y, pr2y[1]);
                tt = fmaf(m0, __log2f(m0), m1 * __log2f(m1));
                lacc = fmaf(__shfl_sync(0xffffffffu, om1, s), tt, lacc);
            }
            for (int s = r2 + 1; s <= r3; s++) {
                float2 ps = s_pb[s][lane];
                float m0 = fmaf(0.5f, ps.x, pr2x[0]);
                float m1 = fmaf(0.5f, ps.y, pr2y[0]);
                float tt = fmaf(m0, __log2f(m0), m1 * __log2f(m1));
                lacc = fmaf(__shfl_sync(0xffffffffu, om0, s), tt, lacc);
                m0 = fmaf(0.5f, ps.x, pr2x[1]);
                m1 = fmaf(0.5f, ps.y, pr2y[1]);
                tt = fmaf(m0, __log2f(m0), m1 * __log2f(m1));
                lacc = fmaf(__shfl_sync(0xffffffffu, om1, s), tt, lacc);
                m0 = fmaf(0.5f, ps.x, pr2x[2]);
                m1 = fmaf(0.5f, ps.y, pr2y[2]);
                tt = fmaf(m0, __log2f(m0), m1 * __log2f(m1));
                lacc = fmaf(__shfl_sync(0xffffffffu, om2, s), tt, lacc);
            }
            for (int s = r3 + 1; s < R_; s++) {
                float2 ps = s_pb[s][lane];
                float m0 = fmaf(0.5f, ps.x, pr2x[0]);
                float m1 = fmaf(0.5f, ps.y, pr2y[0]);
                float tt = fmaf(m0, __log2f(m0), m1 * __log2f(m1));
                lacc = fmaf(__shfl_sync(0xffffffffu, om0, s), tt, lacc);
                m0 = fmaf(0.5f, ps.x, pr2x[1]);
                m1 = fmaf(0.5f, ps.y, pr2y[1]);
                tt = fmaf(m0, __log2f(m0), m1 * __log2f(m1));
                lacc = fmaf(__shfl_sync(0xffffffffu, om1, s), tt, lacc);
                m0 = fmaf(0.5f, ps.x, pr2x[2]);
                m1 = fmaf(0.5f, ps.y, pr2y[2]);
                tt = fmaf(m0, __log2f(m0), m1 * __log2f(m1));
                lacc = fmaf(__shfl_sync(0xffffffffu, om2, s), tt, lacc);
                m0 = fmaf(0.5f, ps.x, pr2x[3]);
                m1 = fmaf(0.5f, ps.y, pr2y[3]);
                tt = fmaf(m0, __log2f(m0), m1 * __log2f(m1));
                lacc = fmaf(__shfl_sync(0xffffffffu, om3, s), tt, lacc);
            }
        }
    }

    // ---- final reduction + last-CTA writeout (log2 domain, scale once) ----
#pragma unroll
    for (int off = 16; off; off >>= 1)
        lacc += __shfl_xor_sync(0xffffffffu, lacc, off);
    if (lane == 0) s_red[wid] = fmaf(0.5f, eacc, -lacc) * LN2;
    __syncthreads();
    if (tid == 0) {
        float a = 0.f;
#pragma unroll
        for (int i = 0; i < 8; i++) a += s_red[i];
        atomicAdd(&g_acc, (double)a);
        __threadfence();
        unsigned int ticket = atomicAdd(&g_done, 1u);
        if (ticket == gridDim.x - 1) {
            double total = *(volatile double*)&g_acc;
            gout[0] = (float)(total / (496.0 + 1e-8));
        }
    }
}

extern "C" void kernel_launch(void* const* d_in, const int* in_sizes, int n_in,
                              void* d_out, int out_size) {
    const float* m = (const float*)d_in[0];
    const float* w = (const float*)d_in[1];
    const float* p = (const float*)d_in[2];
    const float* c = (const float*)d_in[3];
    float* out = (float*)d_out;
    (void)in_sizes; (void)n_in; (void)out_size;

    sheaf_setup_kernel<<<4, 256>>>(c);
    sheaf_kernel<<<BT / TPC, 256>>>(m, w, p, c, out);
}